// round 6
// baseline (speedup 1.0000x reference)
#include <cuda_runtime.h>
#include <math.h>

// DRMM: B=32, D=8, QL=16, DL=512, E=300, V=50000
// One CTA per (b,doc). Doc embeddings staged in smem via coalesced
// cp.async.cg (E chunked x15, double-buffered); 2 doc tokens per thread;
// dots via packed fma.rn.f32x2. Query tile q-major in smem (broadcast LDS).

#define EPSQ 1e-8f

namespace {
constexpr int QL = 16;
constexpr int DL = 512;
constexpr int E  = 300;
constexpr int EC = 20;            // floats per E-chunk
constexpr int NC = 15;            // chunks (15*20 = 300)
constexpr int F4 = 5;             // float4 per chunk-row
constexpr int DBUF = DL * EC;     // floats per staging buffer (10240)
constexpr int NK = (DL * F4) / 256;  // cp.async per thread per chunk = 10
}

__device__ __forceinline__ void fma2(unsigned long long& d,
                                     unsigned long long a,
                                     unsigned long long b) {
    asm("fma.rn.f32x2 %0, %1, %2, %0;" : "+l"(d) : "l"(a), "l"(b));
}
__device__ __forceinline__ float psum(unsigned long long v) {
    return __uint_as_float((unsigned)v) + __uint_as_float((unsigned)(v >> 32));
}
__device__ __forceinline__ void cp16(unsigned dst, const void* src) {
    asm volatile("cp.async.cg.shared.global [%0], [%1], 16;" :: "r"(dst), "l"(src));
}
__device__ __forceinline__ void cp_commit() {
    asm volatile("cp.async.commit_group;");
}
template <int N> __device__ __forceinline__ void cp_wait() {
    asm volatile("cp.async.wait_group %0;" :: "n"(N));
}

__global__ void __launch_bounds__(256, 2) drmm_kernel(
    const int*   __restrict__ bq,     // [32,16]
    const int*   __restrict__ bd,     // [32,8,512]
    const float* __restrict__ emb,    // [50000,300]
    const float* __restrict__ w_g,    // [300]
    const float* __restrict__ b_g,
    const float* __restrict__ w1,     // [5]
    const float* __restrict__ b1,
    const float* __restrict__ w2,
    const float* __restrict__ b2,
    const float* __restrict__ w_o,
    const float* __restrict__ b_o,
    float*       __restrict__ out)    // [32,8]
{
    __shared__ float qs[QL * E];          // q-major query tile (19.2 KB)
    __shared__ float qns[QL], tws[QL], gts[QL], fv[QL];
    __shared__ float red[QL][8];
    __shared__ float w1s[5];
    extern __shared__ float dbuf[];       // [2][DBUF] doc staging (80 KB)

    const int tid = threadIdx.x;
    const int n   = blockIdx.x;
    const int b   = n >> 3;

    // ---- coop copy of 16 query rows ----
    {
        const int* qrow = bq + b * QL;
        for (int i = tid; i < QL * 75; i += 256) {
            const int q = i / 75, f = i - q * 75;
            const int tok = qrow[q];
            ((float4*)qs)[q * 75 + f] =
                __ldg((const float4*)(emb + (size_t)tok * E) + f);
        }
    }
    if (tid < 5) w1s[tid] = w1[tid];

    // ---- precompute staging src/dst for this thread (10 f4 per chunk) ----
    const int* drow = bd + n * DL;
    int      srcf4[NK];   // emb f4-index base: tok*75 + j
    unsigned dsts[NK];    // smem byte offset within buffer 0
    {
        const unsigned dbase = (unsigned)__cvta_generic_to_shared(dbuf);
        #pragma unroll
        for (int k = 0; k < NK; k++) {
            const int i   = tid + 256 * k;
            const int row = i / F4;
            const int j   = i - row * F4;
            srcf4[k] = __ldg(drow + row) * 75 + j;
            dsts[k]  = dbase + (unsigned)(row * EC + 4 * j) * 4u;
        }
    }
    __syncthreads();

    // ---- query norms + gate (16 lanes per q) ----
    {
        const int q = tid >> 4, l16 = tid & 15;
        float s2 = 0.f, g = 0.f;
        const float* r = qs + q * E;
        for (int e = l16; e < E; e += 16) {
            const float v = r[e];
            s2 = fmaf(v, v, s2);
            g  = fmaf(v, __ldg(w_g + e), g);
        }
        #pragma unroll
        for (int k = 8; k >= 1; k >>= 1) {
            s2 += __shfl_xor_sync(0xffffffffu, s2, k, 16);
            g  += __shfl_xor_sync(0xffffffffu, g,  k, 16);
        }
        if (l16 == 0) { qns[q] = __fsqrt_rn(s2); gts[q] = g + b_g[0]; }
    }

    // ---- prologue: stage chunks 0 and 1 ----
    const float4* ef4 = (const float4*)emb;
    #pragma unroll
    for (int k = 0; k < NK; k++) cp16(dsts[k], ef4 + srcf4[k]);
    cp_commit();
    #pragma unroll
    for (int k = 0; k < NK; k++) cp16(dsts[k] + DBUF * 4u, ef4 + srcf4[k] + F4);
    cp_commit();

    __syncthreads();
    if (tid == 0) {  // softmax over 16 query terms
        float m = gts[0];
        for (int q = 1; q < QL; q++) m = fmaxf(m, gts[q]);
        float den = 0.f;
        for (int q = 0; q < QL; q++) { const float ex = expf(gts[q] - m); tws[q] = ex; den += ex; }
        for (int q = 0; q < QL; q++) tws[q] /= den;
    }

    // ---- main loop over 15 E-chunks ----
    unsigned long long acc[QL][2];
    #pragma unroll
    for (int q = 0; q < QL; q++) { acc[q][0] = 0ull; acc[q][1] = 0ull; }
    unsigned long long nr0 = 0ull, nr1 = 0ull;

    #pragma unroll 1
    for (int c = 0; c < NC; c++) {
        if (c == NC - 1) cp_wait<0>(); else cp_wait<1>();
        __syncthreads();

        const float* dB = dbuf + (c & 1) * DBUF;
        const ulonglong2* d0p = (const ulonglong2*)(dB + tid * EC);
        const ulonglong2* d1p = (const ulonglong2*)(dB + (tid + 256) * EC);
        const char* qb = (const char*)qs + c * (EC * 4);

        #pragma unroll
        for (int j = 0; j < F4; j++) {
            const ulonglong2 u0 = d0p[j];
            const ulonglong2 u1 = d1p[j];
            fma2(nr0, u0.x, u0.x); fma2(nr0, u0.y, u0.y);
            fma2(nr1, u1.x, u1.x); fma2(nr1, u1.y, u1.y);
            #pragma unroll
            for (int q = 0; q < QL; q++) {
                const ulonglong2 qv = *(const ulonglong2*)(qb + q * (E * 4) + j * 16);
                fma2(acc[q][0], qv.x, u0.x); fma2(acc[q][0], qv.y, u0.y);
                fma2(acc[q][1], qv.x, u1.x); fma2(acc[q][1], qv.y, u1.y);
            }
        }
        __syncthreads();

        if (c + 2 < NC) {
            const unsigned boff = (unsigned)((c & 1) * DBUF * 4);
            const int foff = (c + 2) * F4;
            #pragma unroll
            for (int k = 0; k < NK; k++) cp16(dsts[k] + boff, ef4 + srcf4[k] + foff);
            cp_commit();
        }
    }

    // ---- epilogue: cos -> bin -> w1[bin] ----
    const float dn0 = __fsqrt_rn(psum(nr0));
    const float dn1 = __fsqrt_rn(psum(nr1));
    float ws[QL];
    #pragma unroll
    for (int q = 0; q < QL; q++) {
        const float qn = qns[q];
        float s = 0.f;
        const float cs0 = __fdiv_rn(psum(acc[q][0]), fmaxf(qn * dn0, EPSQ));
        const float cs1 = __fdiv_rn(psum(acc[q][1]), fmaxf(qn * dn1, EPSQ));
        if (cs0 >= -1.0f && cs0 <= 1.0f) {
            s += cs0 < -0.5f ? w1s[0]
               : cs0 <  0.0f ? w1s[1]
               : cs0 <  0.5f ? w1s[2]
               : cs0 <  1.0f ? w1s[3] : w1s[4];
        }
        if (cs1 >= -1.0f && cs1 <= 1.0f) {
            s += cs1 < -0.5f ? w1s[0]
               : cs1 <  0.0f ? w1s[1]
               : cs1 <  0.5f ? w1s[2]
               : cs1 <  1.0f ? w1s[3] : w1s[4];
        }
        ws[q] = s;
    }

    // ---- deterministic reduction ----
    const int lane = tid & 31, wid = tid >> 5;
    #pragma unroll
    for (int q = 0; q < QL; q++) {
        float v = ws[q];
        v += __shfl_xor_sync(0xffffffffu, v, 16);
        v += __shfl_xor_sync(0xffffffffu, v, 8);
        v += __shfl_xor_sync(0xffffffffu, v, 4);
        v += __shfl_xor_sync(0xffffffffu, v, 2);
        v += __shfl_xor_sync(0xffffffffu, v, 1);
        if (lane == 0) red[q][wid] = v;
    }
    __syncthreads();
    if (tid < QL) {
        float s = 0.f;
        #pragma unroll
        for (int k = 0; k < 8; k++) s += red[tid][k];
        fv[tid] = ((s + b1[0]) * w2[0] + b2[0]) * tws[tid];
    }
    __syncthreads();
    if (tid == 0) {
        float tot = 0.f;
        for (int q = 0; q < QL; q++) tot += fv[q];
        out[n] = tot * w_o[0] + b_o[0];
    }
}

extern "C" void kernel_launch(void* const* d_in, const int* in_sizes, int n_in,
                              void* d_out, int out_size) {
    const int*   bq  = (const int*)  d_in[0];   // batch_queries [32,16]
    const int*   bd  = (const int*)  d_in[2];   // batch_docs [32,8,512]
    const float* emb = (const float*)d_in[4];   // [50000,300]
    const float* wg  = (const float*)d_in[5];
    const float* bg  = (const float*)d_in[6];
    const float* w1  = (const float*)d_in[7];
    const float* b1  = (const float*)d_in[8];
    const float* w2  = (const float*)d_in[9];
    const float* b2  = (const float*)d_in[10];
    const float* wo  = (const float*)d_in[11];
    const float* bo  = (const float*)d_in[12];
    float* out = (float*)d_out;                 // [32,8]

    const int smem = 2 * DBUF * (int)sizeof(float);   // 81920 B dynamic
    cudaFuncSetAttribute(drmm_kernel, cudaFuncAttributeMaxDynamicSharedMemorySize, smem);
    drmm_kernel<<<256, 256, smem>>>(bq, bd, emb, wg, bg, w1, b1, w2, b2, wo, bo, out);
}

// round 12
// speedup vs baseline: 1.1660x; 1.1660x over previous
#include <cuda_runtime.h>
#include <math.h>

// DRMM: B=32, D=8, QL=16, DL=512, E=300, V=50000
// One CTA per (b,doc), 256 threads. Warp-private cp.async double-buffered
// doc staging (each warp stages its own 64 tokens' E-chunk; no CTA barriers
// in the mainloop, __syncwarp + per-warp wait_group only). 2 tokens/thread,
// packed fma.rn.f32x2 mainloop; q tile q-major in smem (broadcast LDS.128).

#define EPSQ 1e-8f

namespace {
constexpr int QL = 16;
constexpr int DL = 512;
constexpr int E  = 300;
constexpr int EC = 20;               // floats per E-chunk
constexpr int NC = 15;               // chunks
constexpr int F4 = 5;                // float4 per chunk-row
constexpr int WBUF = 64 * EC;        // floats per warp per buffer (1280)
constexpr int BUFB = 8 * WBUF;       // floats per buffer (10240)
constexpr int NK = 10;               // cp.async per lane per chunk (64*5/32)
}

__device__ __forceinline__ void fma2(unsigned long long& d,
                                     unsigned long long a,
                                     unsigned long long b) {
    asm("fma.rn.f32x2 %0, %1, %2, %0;" : "+l"(d) : "l"(a), "l"(b));
}
__device__ __forceinline__ float psum(unsigned long long v) {
    return __uint_as_float((unsigned)v) + __uint_as_float((unsigned)(v >> 32));
}
__device__ __forceinline__ void cp16(unsigned dst, const void* src) {
    asm volatile("cp.async.cg.shared.global [%0], [%1], 16;" :: "r"(dst), "l"(src));
}
__device__ __forceinline__ void cp_commit() {
    asm volatile("cp.async.commit_group;");
}
template <int N> __device__ __forceinline__ void cp_wait() {
    asm volatile("cp.async.wait_group %0;" :: "n"(N));
}

__global__ void __launch_bounds__(256, 2) drmm_kernel(
    const int*   __restrict__ bq,     // [32,16]
    const int*   __restrict__ bd,     // [32,8,512]
    const float* __restrict__ emb,    // [50000,300]
    const float* __restrict__ w_g,    // [300]
    const float* __restrict__ b_g,
    const float* __restrict__ w1,     // [5]
    const float* __restrict__ b1,
    const float* __restrict__ w2,
    const float* __restrict__ b2,
    const float* __restrict__ w_o,
    const float* __restrict__ b_o,
    float*       __restrict__ out)    // [32,8]
{
    __shared__ float qs[QL * E];          // q-major query tile (19.2 KB)
    __shared__ float qns[QL], tws[QL], gts[QL], fv[QL];
    __shared__ float red[QL][8];
    __shared__ float w1s[5];
    extern __shared__ float dbuf[];       // [2][8][64][EC] doc staging (80 KB)

    const int tid  = threadIdx.x;
    const int lane = tid & 31;
    const int warp = tid >> 5;
    const int n    = blockIdx.x;
    const int b    = n >> 3;

    // ---- coop copy of 16 query rows ----
    {
        const int* qrow = bq + b * QL;
        for (int i = tid; i < QL * 75; i += 256) {
            const int q = i / 75, f = i - q * 75;
            const int tok = qrow[q];
            ((float4*)qs)[q * 75 + f] =
                __ldg((const float4*)(emb + (size_t)tok * E) + f);
        }
    }
    if (tid < 5) w1s[tid] = w1[tid];

    // ---- per-lane staging plan: this warp's 64 tokens, 10 cp16 per chunk ----
    const int* drow = bd + n * DL;
    int      srcf4[NK];   // emb float4 index: tok*75 + j
    unsigned dst0[NK];    // smem byte addr in buffer 0
    {
        const unsigned dbase = (unsigned)__cvta_generic_to_shared(dbuf)
                             + (unsigned)warp * (WBUF * 4);
        #pragma unroll
        for (int k = 0; k < NK; k++) {
            const int i   = lane + 32 * k;
            const int row = i / F4;            // 0..63 slot within warp
            const int j   = i - row * F4;      // 0..4
            srcf4[k] = __ldg(drow + warp * 64 + row) * 75 + j;
            dst0[k]  = dbase + (unsigned)(row * (EC * 4) + j * 16);
        }
    }
    __syncthreads();

    // ---- query norms + gate (16 lanes per q) ----
    {
        const int q = tid >> 4, l16 = tid & 15;
        float s2 = 0.f, g = 0.f;
        const float* r = qs + q * E;
        for (int e = l16; e < E; e += 16) {
            const float v = r[e];
            s2 = fmaf(v, v, s2);
            g  = fmaf(v, __ldg(w_g + e), g);
        }
        #pragma unroll
        for (int k = 8; k >= 1; k >>= 1) {
            s2 += __shfl_xor_sync(0xffffffffu, s2, k, 16);
            g  += __shfl_xor_sync(0xffffffffu, g,  k, 16);
        }
        if (l16 == 0) { qns[q] = __fsqrt_rn(s2); gts[q] = g + b_g[0]; }
    }
    __syncthreads();
    if (tid == 0) {  // softmax over 16 query terms
        float m = gts[0];
        for (int q = 1; q < QL; q++) m = fmaxf(m, gts[q]);
        float den = 0.f;
        for (int q = 0; q < QL; q++) { const float ex = expf(gts[q] - m); tws[q] = ex; den += ex; }
        for (int q = 0; q < QL; q++) tws[q] /= den;
    }

    // ---- prologue: stage chunks 0 (buf0) and 1 (buf1) for this warp ----
    const float4* ef4 = (const float4*)emb;
    #pragma unroll
    for (int k = 0; k < NK; k++) cp16(dst0[k], ef4 + srcf4[k]);
    cp_commit();
    #pragma unroll
    for (int k = 0; k < NK; k++) cp16(dst0[k] + BUFB * 4u, ef4 + srcf4[k] + F4);
    cp_commit();

    // ---- main loop over 15 E-chunks: warp-private pipeline, no CTA syncs ----
    unsigned long long acc[QL][2];
    #pragma unroll
    for (int q = 0; q < QL; q++) { acc[q][0] = 0ull; acc[q][1] = 0ull; }
    unsigned long long nr0 = 0ull, nr1 = 0ull;

    #pragma unroll 1
    for (int c = 0; c < NC; c++) {
        if (c == NC - 1) cp_wait<0>(); else cp_wait<1>();
        __syncwarp();

        const float* wb = dbuf + (c & 1) * BUFB + warp * WBUF;
        const ulonglong2* d0p = (const ulonglong2*)(wb + lane * EC);
        const ulonglong2* d1p = (const ulonglong2*)(wb + (lane + 32) * EC);
        const char* qb = (const char*)qs + c * (EC * 4);

        #pragma unroll
        for (int j = 0; j < F4; j++) {
            const ulonglong2 u0 = d0p[j];
            const ulonglong2 u1 = d1p[j];
            fma2(nr0, u0.x, u0.x); fma2(nr0, u0.y, u0.y);
            fma2(nr1, u1.x, u1.x); fma2(nr1, u1.y, u1.y);
            #pragma unroll
            for (int q = 0; q < QL; q++) {
                const ulonglong2 qv = *(const ulonglong2*)(qb + q * (E * 4) + j * 16);
                fma2(acc[q][0], qv.x, u0.x); fma2(acc[q][0], qv.y, u0.y);
                fma2(acc[q][1], qv.x, u1.x); fma2(acc[q][1], qv.y, u1.y);
            }
        }
        __syncwarp();

        if (c + 2 < NC) {
            const unsigned boff = (unsigned)((c & 1) * BUFB * 4);
            const int foff = (c + 2) * F4;
            #pragma unroll
            for (int k = 0; k < NK; k++) cp16(dst0[k] + boff, ef4 + srcf4[k] + foff);
            cp_commit();
        }
    }

    // ---- epilogue: cos -> bin -> w1[bin] ----
    const float dn0 = __fsqrt_rn(psum(nr0));
    const float dn1 = __fsqrt_rn(psum(nr1));
    float ws[QL];
    #pragma unroll
    for (int q = 0; q < QL; q++) {
        const float qn = qns[q];
        float s = 0.f;
        const float cs0 = __fdiv_rn(psum(acc[q][0]), fmaxf(qn * dn0, EPSQ));
        const float cs1 = __fdiv_rn(psum(acc[q][1]), fmaxf(qn * dn1, EPSQ));
        if (cs0 >= -1.0f && cs0 <= 1.0f) {
            s += cs0 < -0.5f ? w1s[0]
               : cs0 <  0.0f ? w1s[1]
               : cs0 <  0.5f ? w1s[2]
               : cs0 <  1.0f ? w1s[3] : w1s[4];
        }
        if (cs1 >= -1.0f && cs1 <= 1.0f) {
            s += cs1 < -0.5f ? w1s[0]
               : cs1 <  0.0f ? w1s[1]
               : cs1 <  0.5f ? w1s[2]
               : cs1 <  1.0f ? w1s[3] : w1s[4];
        }
        ws[q] = s;
    }

    // ---- deterministic reduction ----
    #pragma unroll
    for (int q = 0; q < QL; q++) {
        float v = ws[q];
        v += __shfl_xor_sync(0xffffffffu, v, 16);
        v += __shfl_xor_sync(0xffffffffu, v, 8);
        v += __shfl_xor_sync(0xffffffffu, v, 4);
        v += __shfl_xor_sync(0xffffffffu, v, 2);
        v += __shfl_xor_sync(0xffffffffu, v, 1);
        if (lane == 0) red[q][warp] = v;
    }
    __syncthreads();
    if (tid < QL) {
        float s = 0.f;
        #pragma unroll
        for (int k = 0; k < 8; k++) s += red[tid][k];
        fv[tid] = ((s + b1[0]) * w2[0] + b2[0]) * tws[tid];
    }
    __syncthreads();
    if (tid == 0) {
        float tot = 0.f;
        for (int q = 0; q < QL; q++) tot += fv[q];
        out[n] = tot * w_o[0] + b_o[0];
    }
}

extern "C" void kernel_launch(void* const* d_in, const int* in_sizes, int n_in,
                              void* d_out, int out_size) {
    const int*   bq  = (const int*)  d_in[0];   // batch_queries [32,16]
    const int*   bd  = (const int*)  d_in[2];   // batch_docs [32,8,512]
    const float* emb = (const float*)d_in[4];   // [50000,300]
    const float* wg  = (const float*)d_in[5];
    const float* bg  = (const float*)d_in[6];
    const float* w1  = (const float*)d_in[7];
    const float* b1  = (const float*)d_in[8];
    const float* w2  = (const float*)d_in[9];
    const float* b2  = (const float*)d_in[10];
    const float* wo  = (const float*)d_in[11];
    const float* bo  = (const float*)d_in[12];
    float* out = (float*)d_out;                 // [32,8]

    const int smem = 2 * BUFB * (int)sizeof(float);   // 81920 B dynamic
    cudaFuncSetAttribute(drmm_kernel, cudaFuncAttributeMaxDynamicSharedMemorySize, smem);
    drmm_kernel<<<256, 256, smem>>>(bq, bd, emb, wg, bg, w1, b1, w2, b2, wo, bo, out);
}